// round 2
// baseline (speedup 1.0000x reference)
#include <cuda_runtime.h>
#include <cstdint>

// Problem dims
#define B_  32
#define L_  2048
#define IN_ 512
#define H_  512
#define C_  1000
#define LH  (L_ * H_)        // 1048576
#define M_  (B_ * L_)        // 65536

// ---------------------------------------------------------------------------
// Generic fp32 GEMM:  C[M,N] = A[M,K] @ Bmat[N,K]^T + bias[N]
// A row-major, Bmat row-major (N x K)  -> classic 128x128x8 tiled SGEMM.
// M is always a multiple of 128 here; N may be ragged (C_=1000).
// ---------------------------------------------------------------------------
#define BM 128
#define BN 128
#define BK 8
#define TM 8
#define TN 8

__global__ __launch_bounds__(256) void sgemm_bias_kernel(
    int M, int N, int K,
    const float* __restrict__ A,
    const float* __restrict__ Bmat,
    const float* __restrict__ bias,
    float* __restrict__ C)
{
    __shared__ float As[BK][BM];
    __shared__ float Bs[BK][BN];

    const int mTile = blockIdx.y * BM;
    const int nTile = blockIdx.x * BN;
    const int tid   = threadIdx.x;

    const int aRow = tid >> 1;            // 0..127
    const int aK   = (tid & 1) * 4;       // 0 or 4
    const int bRow = tid >> 1;
    const int bK   = (tid & 1) * 4;

    const int threadCol = tid & 15;       // 0..15
    const int threadRow = tid >> 4;       // 0..15

    float acc[TM][TN] = {};
    float regM[TM], regN[TN];

    for (int kb = 0; kb < K; kb += BK) {
        // A tile (no M/K guards needed: M%128==0, K%8==0)
        float4 a4 = *(const float4*)&A[(size_t)(mTile + aRow) * K + kb + aK];
        As[aK + 0][aRow] = a4.x;
        As[aK + 1][aRow] = a4.y;
        As[aK + 2][aRow] = a4.z;
        As[aK + 3][aRow] = a4.w;
        // B tile (guard ragged N)
        float4 b4 = make_float4(0.f, 0.f, 0.f, 0.f);
        if (nTile + bRow < N)
            b4 = *(const float4*)&Bmat[(size_t)(nTile + bRow) * K + kb + bK];
        Bs[bK + 0][bRow] = b4.x;
        Bs[bK + 1][bRow] = b4.y;
        Bs[bK + 2][bRow] = b4.z;
        Bs[bK + 3][bRow] = b4.w;
        __syncthreads();

        #pragma unroll
        for (int k = 0; k < BK; k++) {
            #pragma unroll
            for (int i = 0; i < TM; i++) regM[i] = As[k][threadRow * TM + i];
            #pragma unroll
            for (int j = 0; j < TN; j++) regN[j] = Bs[k][threadCol * TN + j];
            #pragma unroll
            for (int i = 0; i < TM; i++)
                #pragma unroll
                for (int j = 0; j < TN; j++)
                    acc[i][j] += regM[i] * regN[j];
        }
        __syncthreads();
    }

    #pragma unroll
    for (int i = 0; i < TM; i++) {
        const int row = mTile + threadRow * TM + i;
        #pragma unroll
        for (int j = 0; j < TN; j++) {
            const int col = nTile + threadCol * TN + j;
            if (col < N)
                C[(size_t)row * N + col] = acc[i][j] + bias[col];
        }
    }
}

// ---------------------------------------------------------------------------
// Persistent recurrence kernel.
//   hn (B,L,H) initially holds x_proj; step t reads h_{t-1} from hn[:,t-1,:]
//   (t=0: from hidden[:,0,:]) and xp from hn[:,t,:], then overwrites
//   hn[:,t,:] with h_t.  Global software barrier per step.
// Grid: 128 CTAs (<= #SMs -> single wave, all resident).
//   CTA = (column group of 16, batch group of 8). Wh slice stationary in smem.
//   warp = local batch; lane = (col 0..15, K-half 0..1); shfl-reduce halves.
// ---------------------------------------------------------------------------
#define RG 128
#define RT 256
#define WS_STRIDE 516   // 512 + 4 pad: odd in float4 units -> conflict-free LDS.128
#define HS_STRIDE 512   // broadcast reads / stride-1 writes: no pad needed

__device__ unsigned g_bar_arrive = 0;
__device__ unsigned g_bar_gen    = 0;

__global__ __launch_bounds__(RT) void rnn_scan_kernel(
    const float* __restrict__ hidden,
    const float* __restrict__ Wh,
    const float* __restrict__ bh,
    float* __restrict__ hn)
{
    extern __shared__ float smem[];
    float* ws  = smem;                       // 16 x WS_STRIDE
    float* hs  = smem + 16 * WS_STRIDE;      // 8 x HS_STRIDE
    float* bhs = hs + 8 * HS_STRIDE;         // 16

    const int cg = blockIdx.x & 31;          // column group 0..31
    const int bg = blockIdx.x >> 5;          // batch group 0..3
    const int c0 = cg * 16;
    const int b0 = bg * 8;

    const int tid   = threadIdx.x;
    const int w     = tid >> 5;              // warp = local batch 0..7
    const int lane  = tid & 31;
    const int col_l = lane & 15;
    const int kh    = lane >> 4;             // K-half

    // Stationary Wh slice + bias
    for (int i = tid; i < 16 * 512; i += RT) {
        const int r = i >> 9;
        const int k = i & 511;
        ws[r * WS_STRIDE + k] = Wh[(size_t)(c0 + r) * 512 + k];
    }
    if (tid < 16) bhs[tid] = bh[c0 + tid];

    const int b = b0 + w;

    for (int t = 0; t < L_; t++) {
        // ---- stage h_{t-1} for this CTA's 8 batches (coalesced) ----
        if (t == 0) {
            for (int i = tid; i < 8 * 512; i += RT) {
                const int j = i >> 9, k = i & 511;
                hs[j * HS_STRIDE + k] = hidden[(size_t)(b0 + j) * LH + k];
            }
        } else {
            const float* hprev = hn + (size_t)(t - 1) * H_;
            for (int i = tid; i < 8 * 512; i += RT) {
                const int j = i >> 9, k = i & 511;
                // written by other SMs last step -> bypass L1
                hs[j * HS_STRIDE + k] = __ldcg(&hprev[(size_t)(b0 + j) * LH + k]);
            }
        }
        // prefetch x_proj element for my output (hides L2 latency behind FMAs)
        const size_t out_idx = (size_t)b * LH + (size_t)t * H_ + c0 + col_l;
        float xp = 0.f;
        if (kh == 0) xp = hn[out_idx];
        __syncthreads();

        // ---- 256 FMAs per lane: one column, one K-half ----
        const float* hrow  = &hs[w * HS_STRIDE + kh * 256];
        const float* wbase = &ws[col_l * WS_STRIDE + kh * 256];
        float a0 = 0.f, a1 = 0.f, a2 = 0.f, a3 = 0.f;
        #pragma unroll
        for (int k = 0; k < 256; k += 4) {
            const float4 h4 = *(const float4*)&hrow[k];   // lane-uniform broadcast
            const float4 w4 = *(const float4*)&wbase[k];  // conflict-free (odd stride/4)
            a0 += h4.x * w4.x;
            a1 += h4.y * w4.y;
            a2 += h4.z * w4.z;
            a3 += h4.w * w4.w;
        }
        float acc = (a0 + a1) + (a2 + a3);
        acc += __shfl_down_sync(0xffffffffu, acc, 16);     // combine K-halves

        if (kh == 0) {
            const float hv = tanhf(acc + xp + bhs[col_l]);
            hn[out_idx] = hv;
        }

        // ---- grid barrier (sense via monotone generation counter) ----
        if (t != L_ - 1) {
            __threadfence();
            __syncthreads();
            if (tid == 0) {
                const unsigned gen = *(volatile unsigned*)&g_bar_gen;
                const unsigned tk  = atomicAdd(&g_bar_arrive, 1u);
                if (tk == RG - 1) {
                    g_bar_arrive = 0;
                    __threadfence();
                    atomicAdd(&g_bar_gen, 1u);
                } else {
                    while (*(volatile unsigned*)&g_bar_gen == gen) { __nanosleep(64); }
                    __threadfence();
                }
            }
            __syncthreads();
        }
    }
}

// ---------------------------------------------------------------------------
// d_out layout: [ output (B,L,C) = 65,536,000 f32 ][ h_n (B,L,H) = 33,554,432 f32 ]
// The h_n region doubles as x_proj scratch (overwritten in place by the scan).
// ---------------------------------------------------------------------------
extern "C" void kernel_launch(void* const* d_in, const int* in_sizes, int n_in,
                              void* d_out, int out_size)
{
    const float* inputs = (const float*)d_in[0];  // (B,L,IN)
    const float* hidden = (const float*)d_in[1];  // (B,L,H) -- only [:,0,:] used
    const float* Wi     = (const float*)d_in[2];  // (H,IN)
    const float* bi     = (const float*)d_in[3];  // (H)
    const float* Wh     = (const float*)d_in[4];  // (H,H)
    const float* bh     = (const float*)d_in[5];  // (H)
    const float* Wo     = (const float*)d_in[6];  // (C,H)
    const float* bo     = (const float*)d_in[7];  // (C)

    float* out = (float*)d_out;
    float* hn  = out + (size_t)M_ * C_;

    // 1) x_proj = inputs @ Wi^T + bi  -> hn region
    {
        dim3 grid(H_ / BN, M_ / BM);   // (4, 512)
        sgemm_bias_kernel<<<grid, 256>>>(M_, H_, IN_, inputs, Wi, bi, hn);
    }

    // 2) sequential scan (persistent, 1 launch, 2048 steps)
    {
        const size_t smem_bytes = (16 * WS_STRIDE + 8 * HS_STRIDE + 16) * sizeof(float);
        cudaFuncSetAttribute(rnn_scan_kernel,
                             cudaFuncAttributeMaxDynamicSharedMemorySize,
                             (int)smem_bytes);
        rnn_scan_kernel<<<RG, RT, smem_bytes>>>(hidden, Wh, bh, hn);
    }

    // 3) output = h_n @ Wo^T + bo
    {
        dim3 grid((C_ + BN - 1) / BN, M_ / BM);  // (8, 512)
        sgemm_bias_kernel<<<grid, 256>>>(M_, C_, H_, hn, Wo, bo, out);
    }
}

// round 5
// speedup vs baseline: 1.5692x; 1.5692x over previous
#include <cuda_runtime.h>
#include <cstdint>

// Problem dims
#define B_  32
#define L_  2048
#define IN_ 512
#define H_  512
#define C_  1000
#define LH  (L_ * H_)        // 1048576
#define M_  (B_ * L_)        // 65536

// ---------------------------------------------------------------------------
// Generic fp32 GEMM:  C[M,N] = A[M,K] @ Bmat[N,K]^T + bias[N]   (unchanged R2)
// ---------------------------------------------------------------------------
#define BM 128
#define BN 128
#define BK 8
#define TM 8
#define TN 8

__global__ __launch_bounds__(256) void sgemm_bias_kernel(
    int M, int N, int K,
    const float* __restrict__ A,
    const float* __restrict__ Bmat,
    const float* __restrict__ bias,
    float* __restrict__ C)
{
    __shared__ float As[BK][BM];
    __shared__ float Bs[BK][BN];

    const int mTile = blockIdx.y * BM;
    const int nTile = blockIdx.x * BN;
    const int tid   = threadIdx.x;

    const int aRow = tid >> 1;
    const int aK   = (tid & 1) * 4;
    const int bRow = tid >> 1;
    const int bK   = (tid & 1) * 4;

    const int threadCol = tid & 15;
    const int threadRow = tid >> 4;

    float acc[TM][TN] = {};
    float regM[TM], regN[TN];

    for (int kb = 0; kb < K; kb += BK) {
        float4 a4 = *(const float4*)&A[(size_t)(mTile + aRow) * K + kb + aK];
        As[aK + 0][aRow] = a4.x;
        As[aK + 1][aRow] = a4.y;
        As[aK + 2][aRow] = a4.z;
        As[aK + 3][aRow] = a4.w;
        float4 b4 = make_float4(0.f, 0.f, 0.f, 0.f);
        if (nTile + bRow < N)
            b4 = *(const float4*)&Bmat[(size_t)(nTile + bRow) * K + kb + bK];
        Bs[bK + 0][bRow] = b4.x;
        Bs[bK + 1][bRow] = b4.y;
        Bs[bK + 2][bRow] = b4.z;
        Bs[bK + 3][bRow] = b4.w;
        __syncthreads();

        #pragma unroll
        for (int k = 0; k < BK; k++) {
            #pragma unroll
            for (int i = 0; i < TM; i++) regM[i] = As[k][threadRow * TM + i];
            #pragma unroll
            for (int j = 0; j < TN; j++) regN[j] = Bs[k][threadCol * TN + j];
            #pragma unroll
            for (int i = 0; i < TM; i++)
                #pragma unroll
                for (int j = 0; j < TN; j++)
                    acc[i][j] += regM[i] * regN[j];
        }
        __syncthreads();
    }

    #pragma unroll
    for (int i = 0; i < TM; i++) {
        const int row = mTile + threadRow * TM + i;
        #pragma unroll
        for (int j = 0; j < TN; j++) {
            const int col = nTile + threadCol * TN + j;
            if (col < N)
                C[(size_t)row * N + col] = acc[i][j] + bias[col];
        }
    }
}

// ---------------------------------------------------------------------------
// Cluster-local recurrence scan.
//   16 clusters x 8 CTAs (grid 128, single wave). Cluster cl owns batches
//   {2cl, 2cl+1}. CTA rank r owns columns [64r, 64r+64): Wh slice stationary
//   in smem (64 x 516 pad, 132KB). Per step each CTA computes its 128 outputs
//   (2 batches x 64 cols), broadcasts them to all 8 cluster CTAs' h buffers
//   via DSMEM st.shared::cluster (double buffered), one barrier.cluster/step.
//   No global sync anywhere -> no L2 in the dependence chain.
//
//   hn (B,L,H) initially holds x_proj (from GEMM1); each step reads xp there
//   and overwrites in place with h_t.
// ---------------------------------------------------------------------------
#define CLUSTER_N 8
#define SCAN_T    256
#define WS2       516                 // 516 % 32 == 4 -> conflict-free LDS.128

// smem floats: ws 64*516 | hs 2 phases * 2 batches * 512 | bhs 64
#define WS_FLOATS   (64 * WS2)        // 33024
#define HS_FLOATS   (2 * 2 * 512)     // 2048
#define SMEM_FLOATS (WS_FLOATS + HS_FLOATS + 64)

__device__ __forceinline__ uint32_t smem_u32(const void* p) {
    uint32_t a;
    asm("{ .reg .u64 t; cvta.to.shared.u64 t, %1; cvt.u32.u64 %0, t; }"
        : "=r"(a) : "l"(p));
    return a;
}

__global__ void __cluster_dims__(CLUSTER_N, 1, 1) __launch_bounds__(SCAN_T)
rnn_scan_cluster_kernel(
    const float* __restrict__ hidden,
    const float* __restrict__ Wh,
    const float* __restrict__ bh,
    float* __restrict__ hn)
{
    extern __shared__ float sm[];
    float* ws  = sm;                      // [64][WS2]
    float* hs  = sm + WS_FLOATS;          // [2 phase][2 batch][512]
    float* bhs = hs + HS_FLOATS;          // [64]

    uint32_t rank;
    asm("mov.u32 %0, %%cluster_ctarank;" : "=r"(rank));
    const int cl = blockIdx.x >> 3;       // cluster id (contiguous ranks)
    const int b0 = cl * 2;                // 2 batches per cluster
    const int c0 = (int)rank * 64;        // my 64 columns

    const int tid  = threadIdx.x;
    const int warp = tid >> 5;
    const int lane = tid & 31;
    const int c8   = lane & 7;            // col within warp's 8
    const int q    = lane >> 3;           // K-quarter 0..3
    const int col  = warp * 8 + c8;       // 0..63
    const int cg   = c0 + col;            // global column 0..511

    // ---- load stationary Wh slice (float4) ----
    for (int i = tid; i < 64 * 128; i += SCAN_T) {     // 8192 float4s
        const int r  = i >> 7;
        const int f4 = (i & 127) * 4;
        *(float4*)&ws[r * WS2 + f4] =
            *(const float4*)&Wh[(size_t)(c0 + r) * 512 + f4];
    }
    if (tid < 64) bhs[tid] = bh[c0 + tid];

    // ---- initial h0 into phase-0 buffer (both batches, full 512) ----
    for (int i = tid; i < 2 * 128; i += SCAN_T) {      // 256 float4s
        const int b  = i >> 7;
        const int f4 = (i & 127) * 4;
        *(float4*)&hs[b * 512 + f4] =
            *(const float4*)&hidden[(size_t)(b0 + b) * LH + f4];
    }
    __syncthreads();

    // ---- precompute peer DSMEM base addresses of hs (symmetric layout) ----
    const uint32_t hs_local = smem_u32(hs);
    uint32_t peer_hs[CLUSTER_N];
    #pragma unroll
    for (int r = 0; r < CLUSTER_N; r++) {
        asm("mapa.shared::cluster.u32 %0, %1, %2;"
            : "=r"(peer_hs[r]) : "r"(hs_local), "r"(r));
    }

    const bool owner = (lane < 8);        // q==0 lanes hold reduced results
    const float bias_c = owner ? bhs[col] : 0.f;

    // prefetch xp for t=0
    float xp0 = 0.f, xp1 = 0.f;
    if (owner) {
        xp0 = __ldg(&hn[(size_t)(b0 + 0) * LH + cg]);
        xp1 = __ldg(&hn[(size_t)(b0 + 1) * LH + cg]);
    }

    for (int t = 0; t < L_; t++) {
        const int p = t & 1;
        const float* hrow0 = &hs[p * 1024 + 0   + q * 128];
        const float* hrow1 = &hs[p * 1024 + 512 + q * 128];
        const float* wbase = &ws[col * WS2 + q * 128];

        float a00 = 0.f, a01 = 0.f, a10 = 0.f, a11 = 0.f;
        #pragma unroll 8
        for (int k = 0; k < 128; k += 4) {
            const float4 w4 = *(const float4*)&wbase[k];
            const float4 h0 = *(const float4*)&hrow0[k];   // 8-lane broadcast
            const float4 h1 = *(const float4*)&hrow1[k];
            a00 += w4.x * h0.x; a01 += w4.y * h0.y;
            a00 += w4.z * h0.z; a01 += w4.w * h0.w;
            a10 += w4.x * h1.x; a11 += w4.y * h1.y;
            a10 += w4.z * h1.z; a11 += w4.w * h1.w;
        }
        float acc0 = a00 + a01;
        float acc1 = a10 + a11;
        // combine the 4 K-quarters (lanes L, L+8, L+16, L+24)
        acc0 += __shfl_down_sync(0xffffffffu, acc0, 16);
        acc1 += __shfl_down_sync(0xffffffffu, acc1, 16);
        acc0 += __shfl_down_sync(0xffffffffu, acc0, 8);
        acc1 += __shfl_down_sync(0xffffffffu, acc1, 8);

        if (owner) {
            const float hv0 = tanhf(acc0 + xp0 + bias_c);
            const float hv1 = tanhf(acc1 + xp1 + bias_c);

            // h_n output (also GEMM3 input)
            hn[(size_t)(b0 + 0) * LH + (size_t)t * H_ + cg] = hv0;
            hn[(size_t)(b0 + 1) * LH + (size_t)t * H_ + cg] = hv1;

            if (t != L_ - 1) {
                // broadcast into every cluster CTA's next-phase h buffer
                const uint32_t off0 = (uint32_t)(((p ^ 1) * 1024 + cg) * 4);
                const uint32_t off1 = off0 + 512 * 4;
                #pragma unroll
                for (int r = 0; r < CLUSTER_N; r++) {
                    asm volatile("st.shared::cluster.f32 [%0], %1;"
                                 :: "r"(peer_hs[r] + off0), "f"(hv0) : "memory");
                    asm volatile("st.shared::cluster.f32 [%0], %1;"
                                 :: "r"(peer_hs[r] + off1), "f"(hv1) : "memory");
                }
            }
        }

        if (t != L_ - 1) {
            // release my stores, then overlap xp prefetch with peers' arrival
            asm volatile("barrier.cluster.arrive.aligned;" ::: "memory");
            if (owner) {
                xp0 = __ldg(&hn[(size_t)(b0 + 0) * LH + (size_t)(t + 1) * H_ + cg]);
                xp1 = __ldg(&hn[(size_t)(b0 + 1) * LH + (size_t)(t + 1) * H_ + cg]);
            }
            asm volatile("barrier.cluster.wait.aligned;" ::: "memory");
        }
    }
}

// ---------------------------------------------------------------------------
// d_out layout: [ output (B,L,C) ][ h_n (B,L,H) ];  h_n doubles as x_proj.
// ---------------------------------------------------------------------------
extern "C" void kernel_launch(void* const* d_in, const int* in_sizes, int n_in,
                              void* d_out, int out_size)
{
    const float* inputs = (const float*)d_in[0];
    const float* hidden = (const float*)d_in[1];
    const float* Wi     = (const float*)d_in[2];
    const float* bi     = (const float*)d_in[3];
    const float* Wh     = (const float*)d_in[4];
    const float* bh     = (const float*)d_in[5];
    const float* Wo     = (const float*)d_in[6];
    const float* bo     = (const float*)d_in[7];

    float* out = (float*)d_out;
    float* hn  = out + (size_t)M_ * C_;

    // 1) x_proj = inputs @ Wi^T + bi  -> hn region
    {
        dim3 grid(H_ / BN, M_ / BM);
        sgemm_bias_kernel<<<grid, 256>>>(M_, H_, IN_, inputs, Wi, bi, hn);
    }

    // 2) cluster-local scan (1 launch, 2048 steps, no global sync)
    {
        const size_t smem_bytes = SMEM_FLOATS * sizeof(float);
        static bool attr_set = false;
        cudaFuncSetAttribute(rnn_scan_cluster_kernel,
                             cudaFuncAttributeMaxDynamicSharedMemorySize,
                             (int)smem_bytes);
        (void)attr_set;
        rnn_scan_cluster_kernel<<<16 * CLUSTER_N, SCAN_T, smem_bytes>>>(
            hidden, Wh, bh, hn);
    }

    // 3) output = h_n @ Wo^T + bo
    {
        dim3 grid((C_ + BN - 1) / BN, M_ / BM);
        sgemm_bias_kernel<<<grid, 256>>>(M_, C_, H_, hn, Wo, bo, out);
    }
}